// round 8
// baseline (speedup 1.0000x reference)
#include <cuda_runtime.h>
#include <cstdint>
#include <cstddef>

#define T_STEPS 2048
#define B_SIZE  256
#define I_SIZE  64
#define H_SIZE  128

// Scratch: precomputed input projections x@Wi + bi, layout [T][B][3*H]
__device__ float g_xproj[(size_t)T_STEPS * B_SIZE * 3 * H_SIZE];

__device__ __forceinline__ float sigmoidf_(float x) {
    return 1.0f / (1.0f + __expf(-x));
}
__device__ __forceinline__ float tanhf_(float x) {
    return 1.0f - 2.0f / (1.0f + __expf(2.0f * x));
}

// ---- packed f32x2 helpers (Blackwell FFMA2) --------------------------------
__device__ __forceinline__ unsigned long long fma2_(unsigned long long a,
                                                    unsigned long long b,
                                                    unsigned long long c) {
    unsigned long long d;
    asm("fma.rn.f32x2 %0, %1, %2, %3;" : "=l"(d) : "l"(a), "l"(b), "l"(c));
    return d;
}
__device__ __forceinline__ unsigned long long dup2_(float x) {
    unsigned long long d;
    asm("mov.b64 %0, {%1, %1};" : "=l"(d) : "f"(x));
    return d;
}
__device__ __forceinline__ unsigned long long pack2_(float a, float b) {
    unsigned long long d;
    asm("mov.b64 %0, {%1, %2};" : "=l"(d) : "f"(a), "f"(b));
    return d;
}
__device__ __forceinline__ float2 unpack2_(unsigned long long v) {
    float2 r;
    asm("mov.b64 {%0, %1}, %2;" : "=f"(r.x), "=f"(r.y) : "l"(v));
    return r;
}

// ============================================================================
// Phase 1: xproj[t,b, g*128 + j] = sum_i x[t,b,i] * Wg[i,j] + bg[j]
// Block tile = 64 rows x 128 cols (one gate), 256 threads, 4x8 reg tile,
// inner product packed as f32x2 over the c-dimension.
// ============================================================================
__global__ __launch_bounds__(256, 2) void xproj_kernel(
    const float* __restrict__ x,
    const float* __restrict__ Wir, const float* __restrict__ Wiz, const float* __restrict__ Win,
    const float* __restrict__ bir, const float* __restrict__ biz, const float* __restrict__ bin_)
{
    __shared__ __align__(16) float xs[I_SIZE][68];      // x transposed, 68*4=272=17*16B
    __shared__ __align__(16) float ws[I_SIZE][H_SIZE];
    __shared__ float bs[H_SIZE];

    const int g = blockIdx.y;
    const float* __restrict__ W    = (g == 0) ? Wir : (g == 1) ? Wiz : Win;
    const float* __restrict__ bias = (g == 0) ? bir : (g == 1) ? biz : bin_;

    const int tid = threadIdx.x;
    const size_t r_base = (size_t)blockIdx.x * 64;

    const float* __restrict__ xg = x + r_base * I_SIZE;
    #pragma unroll
    for (int s = 0; s < 16; s++) {
        int idx = tid + 256 * s;
        int row = idx >> 6;
        int i   = idx & 63;
        xs[i][row] = xg[idx];
    }
    #pragma unroll
    for (int s = 0; s < 32; s++) {
        int idx = tid + 256 * s;
        ((float*)ws)[idx] = W[idx];
    }
    if (tid < H_SIZE) bs[tid] = bias[tid];
    __syncthreads();

    const int tr = tid & 15;
    const int tc = tid >> 4;
    const int r0 = tr * 4;
    const int c0 = tc * 8;

    unsigned long long accp[4][4];
    #pragma unroll
    for (int r = 0; r < 4; r++)
        #pragma unroll
        for (int c = 0; c < 4; c++)
            accp[r][c] = 0ull;

    #pragma unroll 8
    for (int k = 0; k < I_SIZE; k++) {
        float4 xa = *(const float4*)&xs[k][r0];
        const ulonglong2* wrow = (const ulonglong2*)&ws[k][c0]; // 32B aligned (c0 % 8 == 0)
        ulonglong2 wp01 = wrow[0];   // pairs (c0,c0+1),(c0+2,c0+3)
        ulonglong2 wp23 = wrow[1];   // pairs (c0+4,c0+5),(c0+6,c0+7)
        unsigned long long xd[4] = {dup2_(xa.x), dup2_(xa.y), dup2_(xa.z), dup2_(xa.w)};
        #pragma unroll
        for (int r = 0; r < 4; r++) {
            accp[r][0] = fma2_(xd[r], wp01.x, accp[r][0]);
            accp[r][1] = fma2_(xd[r], wp01.y, accp[r][1]);
            accp[r][2] = fma2_(xd[r], wp23.x, accp[r][2]);
            accp[r][3] = fma2_(xd[r], wp23.y, accp[r][3]);
        }
    }

    #pragma unroll
    for (int r = 0; r < 4; r++) {
        size_t row = r_base + (size_t)(r0 + r);
        float* op = g_xproj + row * (3 * H_SIZE) + g * H_SIZE + c0;
        float2 p0 = unpack2_(accp[r][0]);
        float2 p1 = unpack2_(accp[r][1]);
        float2 p2 = unpack2_(accp[r][2]);
        float2 p3 = unpack2_(accp[r][3]);
        float4 o0, o1;
        o0.x = p0.x + bs[c0 + 0];
        o0.y = p0.y + bs[c0 + 1];
        o0.z = p1.x + bs[c0 + 2];
        o0.w = p1.y + bs[c0 + 3];
        o1.x = p2.x + bs[c0 + 4];
        o1.y = p2.y + bs[c0 + 5];
        o1.z = p3.x + bs[c0 + 6];
        o1.w = p3.y + bs[c0 + 7];
        *(float4*)(op)     = o0;
        *(float4*)(op + 4) = o1;
    }
}

// ============================================================================
// Phase 2: persistent per-batch GRU recurrence + fused classifier.
// grid = 128 blocks (2 batch rows each), 384 threads.
// thread = (gate g, hidden col j). Wh column lives in regs as 64 f32x2 pairs.
// Inner matmul packed over k: 128 FFMA2 per thread per step.
// ============================================================================
__global__ __launch_bounds__(384, 1) void gru_kernel(
    const float* __restrict__ Whr, const float* __restrict__ Whz, const float* __restrict__ Whn,
    const float* __restrict__ bhn, const float* __restrict__ Wc,  const float* __restrict__ bc,
    float* __restrict__ out)
{
    __shared__ __align__(16) float h_s[2][H_SIZE];
    __shared__ float r_s[2][H_SIZE];
    __shared__ float z_s[2][H_SIZE];
    __shared__ float cls[2][4];

    const int tid = threadIdx.x;
    const int g   = tid >> 7;       // 0=r, 1=z, 2=n
    const int j   = tid & 127;
    const int b0  = blockIdx.x * 2;

    const float* __restrict__ Wh = (g == 0) ? Whr : (g == 1) ? Whz : Whn;

    // Register-resident weight column, packed over k pairs: w2[k] = (Wh[2k][j], Wh[2k+1][j])
    unsigned long long w2[H_SIZE / 2];
    #pragma unroll
    for (int k = 0; k < H_SIZE / 2; k++)
        w2[k] = pack2_(Wh[(2 * k) * H_SIZE + j], Wh[(2 * k + 1) * H_SIZE + j]);

    const float bhn_j = bhn[j];
    const float wc_j  = Wc[j];
    const float bc0   = bc[0];

    if (tid < 2 * H_SIZE) ((float*)h_s)[tid] = 0.0f;   // h0 = 0
    __syncthreads();

    const float* __restrict__ xp = g_xproj + (size_t)b0 * (3 * H_SIZE) + g * H_SIZE + j;
    const size_t step_stride = (size_t)B_SIZE * 3 * H_SIZE;

    const ulonglong2* __restrict__ h0p = (const ulonglong2*)h_s[0];
    const ulonglong2* __restrict__ h1p = (const ulonglong2*)h_s[1];

    for (int t = 0; t < T_STEPS; t++) {
        const float* xpt = xp + (size_t)t * step_stride;
        float x0 = xpt[0];
        float x1 = xpt[3 * H_SIZE];

        // acc[row] = sum_k h[row][k] * Wh[k][j], packed f32x2 over k.
        unsigned long long a0[4] = {0ull, 0ull, 0ull, 0ull};
        unsigned long long a1[4] = {0ull, 0ull, 0ull, 0ull};
        #pragma unroll
        for (int k4 = 0; k4 < H_SIZE / 4; k4++) {
            ulonglong2 v0 = h0p[k4];   // pairs (h[4k4],h[4k4+1]),(h[4k4+2],h[4k4+3])
            ulonglong2 v1 = h1p[k4];
            int s = (k4 & 1) << 1;
            a0[s + 0] = fma2_(v0.x, w2[2 * k4 + 0], a0[s + 0]);
            a0[s + 1] = fma2_(v0.y, w2[2 * k4 + 1], a0[s + 1]);
            a1[s + 0] = fma2_(v1.x, w2[2 * k4 + 0], a1[s + 0]);
            a1[s + 1] = fma2_(v1.y, w2[2 * k4 + 1], a1[s + 1]);
        }
        float2 u00 = unpack2_(a0[0]), u01 = unpack2_(a0[1]);
        float2 u02 = unpack2_(a0[2]), u03 = unpack2_(a0[3]);
        float2 u10 = unpack2_(a1[0]), u11 = unpack2_(a1[1]);
        float2 u12 = unpack2_(a1[2]), u13 = unpack2_(a1[3]);
        float acc0 = ((u00.x + u00.y) + (u01.x + u01.y)) + ((u02.x + u02.y) + (u03.x + u03.y));
        float acc1 = ((u10.x + u10.y) + (u11.x + u11.y)) + ((u12.x + u12.y) + (u13.x + u13.y));

        if (g == 0) {
            r_s[0][j] = sigmoidf_(x0 + acc0);
            r_s[1][j] = sigmoidf_(x1 + acc1);
        } else if (g == 1) {
            z_s[0][j] = sigmoidf_(x0 + acc0);
            z_s[1][j] = sigmoidf_(x1 + acc1);
        }
        __syncthreads();   // r,z ready

        if (g == 2) {
            float h0o = h_s[0][j];
            float h1o = h_s[1][j];
            float n0 = tanhf_(x0 + r_s[0][j] * (acc0 + bhn_j));
            float n1 = tanhf_(x1 + r_s[1][j] * (acc1 + bhn_j));
            float z0 = z_s[0][j];
            float z1 = z_s[1][j];
            float hn0 = (1.0f - z0) * n0 + z0 * h0o;
            float hn1 = (1.0f - z1) * n1 + z1 * h1o;
            h_s[0][j] = hn0;
            h_s[1][j] = hn1;

            // Fused classifier partial: dot(h_new, Wc) via warp reduction.
            float v0 = hn0 * wc_j;
            float v1 = hn1 * wc_j;
            #pragma unroll
            for (int off = 16; off > 0; off >>= 1) {
                v0 += __shfl_down_sync(0xffffffffu, v0, off);
                v1 += __shfl_down_sync(0xffffffffu, v1, off);
            }
            int w4 = (tid >> 5) & 3;
            if ((tid & 31) == 0) { cls[0][w4] = v0; cls[1][w4] = v1; }
        }
        __syncthreads();   // h_new + cls ready

        if (tid < 2) {
            float s = ((cls[tid][0] + cls[tid][1]) + (cls[tid][2] + cls[tid][3])) + bc0;
            out[(size_t)t * B_SIZE + b0 + tid] = sigmoidf_(s);
        }
        // cls re-read happens before gate-2 can rewrite it (rewrite is gated by
        // the next iteration's first __syncthreads, which tid<2 must reach first).
    }
}

// ============================================================================
extern "C" void kernel_launch(void* const* d_in, const int* in_sizes, int n_in,
                              void* d_out, int out_size)
{
    const float* x    = (const float*)d_in[0];
    const float* Wir  = (const float*)d_in[1];
    const float* Wiz  = (const float*)d_in[2];
    const float* Win  = (const float*)d_in[3];
    const float* bir  = (const float*)d_in[4];
    const float* biz  = (const float*)d_in[5];
    const float* bin_ = (const float*)d_in[6];
    const float* Whr  = (const float*)d_in[7];
    const float* Whz  = (const float*)d_in[8];
    const float* Whn  = (const float*)d_in[9];
    const float* bhn  = (const float*)d_in[10];
    const float* Wc   = (const float*)d_in[11];
    const float* bc   = (const float*)d_in[12];
    float* out = (float*)d_out;

    dim3 grid1((T_STEPS * B_SIZE) / 64, 3);
    xproj_kernel<<<grid1, 256>>>(x, Wir, Wiz, Win, bir, biz, bin_);

    gru_kernel<<<B_SIZE / 2, 384>>>(Whr, Whz, Whn, bhn, Wc, bc, out);
}